// round 17
// baseline (speedup 1.0000x reference)
#include <cuda_runtime.h>
#include <cuda_fp16.h>
#include <cstdint>

// VQ quantizer: fp16 hi-only HMMA screen + packed-key top-3 + exact rescue.
// R17: (1) WARP-decoupled persistent work: each warp strides over 32-row
// warp-tiles (16384 items / 3552 warps) -- no __syncthreads in the loop, so
// CTA-coupling of warps to tiles was pure addressing; finer granularity
// smooths the 4-vs-5 tile imbalance (~8% chip idle in R16).
// (2) Gather batched 8-deep (MLP=8). (3) Packed f32x2->f16x2 conversions.
// Mainloop math identical to R15/R16 (validated rel_err=0.0).
//
// Screen: dot_hi = <z_hi,c_hi> via mma.sync. Key: dist''=(||c||^2+256)-2*dot
// (>0 -> uint-orderable); key=(bits&~511)|k; pair-insert top-3 (8 IMNMX/2).
// Rescue (DELTA=0.3): top-2 gap < DELTA -> per-lane exact fp32 rescore;
// top-3 gap < DELTA -> warp-cooperative full exact scan (ballot).
// Exact path: plain ||c||^2, fp32 fmaf, strict <, first-index ties.

#define DQ        64
#define KC        512
#define ROWB      144                       // hi fp16 row: 128B data + 16B pad
#define PACK_BYTES (KC * ROWB)              // 73728
#define SM_NRM    PACK_BYTES                // plain ||c||^2 (exact path + keys)
#define SMEM_TOTAL (SM_NRM + KC * 4)        // 75776
#define THREADS   256
#define WROWS     32                        // rows per warp-tile
#define NCHUNK    (KC / 16)                 // 32
#define NSM       148
#define CTAS      (3 * NSM)                 // 444 persistent CTAs
#define NWARPS    (CTAS * 8)                // 3552 persistent warps
#define DELTA     0.3f
#define OFFS      256.0f

__device__ __align__(16) unsigned char g_cbpack[PACK_BYTES];
__device__ float g_cnorm[KC];               // plain ||c||^2 (NO offset)

// ---------------- helpers ----------------

__device__ __forceinline__ uint32_t smem_u32(const void* p) {
    uint32_t a;
    asm("{ .reg .u64 t; cvta.to.shared.u64 t, %1; cvt.u32.u64 %0, t; }" : "=r"(a) : "l"(p));
    return a;
}

__device__ __forceinline__ uint32_t packh2(float2 f) {
    __half2 h = __float22half2_rn(f);       // single F2FP.PACK
    return *reinterpret_cast<uint32_t*>(&h);
}

#define LDSM4(r0, r1, r2, r3, addr)                                         \
    asm volatile("ldmatrix.sync.aligned.m8n8.x4.shared.b16 {%0,%1,%2,%3}, [%4];" \
        : "=r"(r0), "=r"(r1), "=r"(r2), "=r"(r3) : "r"(addr))

#define MMA16816(c0, c1, c2, c3, a0, a1, a2, a3, b0, b1)                    \
    asm volatile("mma.sync.aligned.m16n8k16.row.col.f32.f16.f16.f32 "       \
        "{%0,%1,%2,%3}, {%4,%5,%6,%7}, {%8,%9}, {%0,%1,%2,%3};"             \
        : "+f"(c0), "+f"(c1), "+f"(c2), "+f"(c3)                            \
        : "r"(a0), "r"(a1), "r"(a2), "r"(a3), "r"(b0), "r"(b1))

// Single sorted top-3 insert (a<=b<=c), 5 IMNMX (warp merges only).
__device__ __forceinline__ void ins3(uint32_t& a, uint32_t& b, uint32_t& c,
                                     uint32_t x) {
    uint32_t h1 = max(a, x); a = min(a, x);
    uint32_t h2 = max(b, h1); b = min(b, h1);
    c = min(c, h2);
}

// Pair insert: merge sorted pair {x,y} into sorted (a<=b<=c). 8 IMNMX.
__device__ __forceinline__ void ins3p(uint32_t& a, uint32_t& b, uint32_t& c,
                                      uint32_t x, uint32_t y) {
    uint32_t mn = min(x, y), mx = max(x, y);
    uint32_t u = max(a, mn); a = min(a, mn);
    uint32_t v = min(b, mx);
    uint32_t w = max(u, v);  b = min(u, v);
    c = min(c, w);
}

// Screen key ONLY (nrmk carries +OFFS, added per chunk). Not the exact path.
__device__ __forceinline__ uint32_t mkkey(float dot, float nrmk, int k) {
    const float d = fmaf(-2.0f, dot, nrmk);
    return (__float_as_uint(d) & ~511u) | (uint32_t)k;
}

// R5 bit-exact offsetless distance (fp32, fixed fmaf order).
__device__ __forceinline__ float exact_dist(const float4* zv, const float* crow_f,
                                            float nrm) {
    const float4* crow = reinterpret_cast<const float4*>(crow_f);
    float s0 = 0.f, s1 = 0.f, s2 = 0.f, s3 = 0.f;
    #pragma unroll
    for (int i = 0; i < 16; i++) {
        float4 c = crow[i]; float4 z = zv[i];
        s0 = fmaf(z.x, c.x, s0); s1 = fmaf(z.y, c.y, s1);
        s2 = fmaf(z.z, c.z, s2); s3 = fmaf(z.w, c.w, s3);
    }
    return fmaf(-2.0f, (s0 + s1) + (s2 + s3), nrm);
}

// ---------------- prep ----------------

__global__ void prep_kernel(const float* __restrict__ cb) {
    const int k = threadIdx.x;
    if (k >= KC) return;
    const float4* row = reinterpret_cast<const float4*>(cb + (size_t)k * DQ);
    uint32_t* dst = reinterpret_cast<uint32_t*>(g_cbpack + (size_t)k * ROWB);
    float s0 = 0.f, s1 = 0.f, s2 = 0.f, s3 = 0.f;
    #pragma unroll
    for (int i = 0; i < 16; i++) {
        float4 f = row[i];
        s0 = fmaf(f.x, f.x, s0); s1 = fmaf(f.y, f.y, s1);
        s2 = fmaf(f.z, f.z, s2); s3 = fmaf(f.w, f.w, s3);
        dst[2*i]     = packh2(make_float2(f.x, f.y));
        dst[2*i + 1] = packh2(make_float2(f.z, f.w));
    }
    g_cnorm[k] = (s0 + s1) + (s2 + s3);     // plain (R5 semantics)
}

// ---------------- main (persistent, warp-decoupled) ----------------

__global__ __launch_bounds__(THREADS, 3)
void vq_main(const float* __restrict__ ze,
             const float* __restrict__ cb,
             float* __restrict__ out,
             int n_wtiles) {
    extern __shared__ char smem[];
    float* snrm = reinterpret_cast<float*>(smem + SM_NRM);

    // ONE-TIME cooperative copy: hi-pack + norms -> SMEM (74 KB).
    {
        const uint4* s0 = reinterpret_cast<const uint4*>(g_cbpack);
        uint4* d0 = reinterpret_cast<uint4*>(smem);
        for (int i = threadIdx.x; i < PACK_BYTES / 16; i += THREADS) d0[i] = s0[i];
        for (int i = threadIdx.x; i < KC; i += THREADS) snrm[i] = g_cnorm[i];
    }
    __syncthreads();

    const int tid  = threadIdx.x;
    const int w    = tid >> 5;              // 0..7
    const int lane = tid & 31;
    const int g    = lane >> 2;
    const int t    = lane & 3;

    const uint32_t smem_u = smem_u32(smem);
    const int      brow = ((lane >> 4) & 1) * 8 + (lane & 7);
    const uint32_t koff = ((lane >> 3) & 1) * 16;
    const uint32_t bwarp = smem_u + (uint32_t)brow * ROWB + koff;

    // Warp-independent persistent loop (no cross-warp coupling; SMEM is
    // read-only after the prolog).
    const int warp_global = blockIdx.x * 8 + w;
    #pragma unroll 1
    for (int wt = warp_global; wt < n_wtiles; wt += NWARPS) {
        const int row_base = wt * WROWS;

        // A fragments (hi only), 2 m-tiles: Ah[mt][kt][2*h + rr]
        uint32_t Ah[2][4][4];
        #pragma unroll
        for (int mt = 0; mt < 2; mt++)
            #pragma unroll
            for (int kt = 0; kt < 4; kt++)
                #pragma unroll
                for (int h = 0; h < 2; h++)
                    #pragma unroll
                    for (int rr = 0; rr < 2; rr++) {
                        const int row = row_base + mt * 16 + g + 8 * rr;
                        const int col = kt * 16 + h * 8 + 2 * t;
                        float2 f = *reinterpret_cast<const float2*>(
                            ze + (size_t)row * DQ + col);
                        Ah[mt][kt][2*h + rr] = packh2(f);
                    }

        // Sorted top-3 keys per row slot (s=2*mt+rr -> row (s>>1)*16+g+8*(s&1)).
        uint32_t K1[4], K2[4], K3[4];
        #pragma unroll
        for (int s = 0; s < 4; s++) { K1[s] = K2[s] = K3[s] = 0xFFFFFFFFu; }

        #pragma unroll 1
        for (int c = 0; c < NCHUNK; c++) {
            const int n0 = c * 16;
            const uint32_t bbase = bwarp + (uint32_t)(n0 * ROWB);

            uint32_t B[4][4];
            #pragma unroll
            for (int kt = 0; kt < 4; kt++)
                LDSM4(B[kt][0], B[kt][1], B[kt][2], B[kt][3], bbase + kt * 32);

            const float2 c0f = *reinterpret_cast<const float2*>(&snrm[n0 + 2 * t]);
            const float2 c1f = *reinterpret_cast<const float2*>(&snrm[n0 + 8 + 2 * t]);
            const float ck0x = c0f.x + OFFS, ck0y = c0f.y + OFFS;
            const float ck1x = c1f.x + OFFS, ck1y = c1f.y + OFFS;

            #pragma unroll
            for (int mt = 0; mt < 2; mt++) {
                float acc[2][4];
                #pragma unroll
                for (int nt = 0; nt < 2; nt++)
                    #pragma unroll
                    for (int q = 0; q < 4; q++) acc[nt][q] = 0.f;

                #pragma unroll
                for (int kt = 0; kt < 4; kt++) {
                    MMA16816(acc[0][0], acc[0][1], acc[0][2], acc[0][3],
                             Ah[mt][kt][0], Ah[mt][kt][1], Ah[mt][kt][2], Ah[mt][kt][3],
                             B[kt][0], B[kt][1]);
                    MMA16816(acc[1][0], acc[1][1], acc[1][2], acc[1][3],
                             Ah[mt][kt][0], Ah[mt][kt][1], Ah[mt][kt][2], Ah[mt][kt][3],
                             B[kt][2], B[kt][3]);
                }

                const int sA = 2 * mt, sB = 2 * mt + 1;
                #pragma unroll
                for (int nt = 0; nt < 2; nt++) {
                    const float cA = nt ? ck1x : ck0x;
                    const float cB = nt ? ck1y : ck0y;
                    const int colA = n0 + nt * 8 + 2 * t;
                    ins3p(K1[sA], K2[sA], K3[sA],
                          mkkey(acc[nt][0], cA, colA),
                          mkkey(acc[nt][1], cB, colA + 1));
                    ins3p(K1[sB], K2[sB], K3[sB],
                          mkkey(acc[nt][2], cA, colA),
                          mkkey(acc[nt][3], cB, colA + 1));
                }
            }
        }

        // Cross-lane merge (lanes 4g..4g+3 share the same 4 rows).
        #pragma unroll
        for (int xo = 1; xo <= 2; xo <<= 1) {
            #pragma unroll
            for (int s = 0; s < 4; s++) {
                uint32_t o1 = __shfl_xor_sync(0xFFFFFFFFu, K1[s], xo);
                uint32_t o2 = __shfl_xor_sync(0xFFFFFFFFu, K2[s], xo);
                uint32_t o3 = __shfl_xor_sync(0xFFFFFFFFu, K3[s], xo);
                ins3p(K1[s], K2[s], K3[s], o1, o2);
                ins3(K1[s], K2[s], K3[s], o3);
            }
        }

        // ---- Resolution: lane 4g+t owns slot t -> row (t>>1)*16+g+8*(t&1). ----
        const int my_row = row_base + (t >> 1) * 16 + g + 8 * (t & 1);
        const uint32_t key1 = K1[t], key2 = K2[t], key3 = K3[t];
        const int rk1 = (int)(key1 & 511u), rk2 = (int)(key2 & 511u);
        const float a1 = __uint_as_float(key1 & ~511u);
        const float a2 = __uint_as_float(key2 & ~511u);
        const float a3 = __uint_as_float(key3 & ~511u);
        int  kw = rk1;
        const bool need_full = (a3 - a1 < DELTA);
        const bool need_pair = !need_full && (a2 - a1 < DELTA);

        // Warp-cooperative full exact scans (rare; ~0.12% of tokens).
        unsigned fmask = __ballot_sync(0xFFFFFFFFu, need_full);
        while (fmask) {
            const int src = __ffs(fmask) - 1;
            fmask &= fmask - 1;
            const int stt = src & 3, sgg = src >> 2;
            const int srow = row_base + (stt >> 1) * 16 + sgg + 8 * (stt & 1);
            float4 zv[16];
            const float4* zp = reinterpret_cast<const float4*>(ze + (size_t)srow * DQ);
            #pragma unroll
            for (int i = 0; i < 16; i++) zv[i] = zp[i];
            float bd = 3.4e38f; int bk = 0;
            const int k0 = lane * 16;
            #pragma unroll 1
            for (int q = 0; q < 16; q++) {
                const int k = k0 + q;
                const float d = exact_dist(zv, cb + (size_t)k * DQ, snrm[k]);
                if (d < bd) { bd = d; bk = k; }
            }
            #pragma unroll
            for (int xo = 16; xo >= 1; xo >>= 1) {
                const float od = __shfl_xor_sync(0xFFFFFFFFu, bd, xo);
                const int   ok = __shfl_xor_sync(0xFFFFFFFFu, bk, xo);
                if (od < bd || (od == bd && ok < bk)) { bd = od; bk = ok; }
            }
            if (lane == src) kw = bk;
        }

        // Per-lane pairwise exact rescore (~5% of tokens).
        if (need_pair) {
            float4 zv[16];
            const float4* zp = reinterpret_cast<const float4*>(ze + (size_t)my_row * DQ);
            #pragma unroll
            for (int i = 0; i < 16; i++) zv[i] = zp[i];
            const float e1 = exact_dist(zv, cb + (size_t)rk1 * DQ, snrm[rk1]);
            const float e2 = exact_dist(zv, cb + (size_t)rk2 * DQ, snrm[rk2]);
            if (e2 < e1 || (e2 == e1 && rk2 < rk1)) kw = rk2;
        }

        // Coalesced gather (cb is L2-resident) + write, batched 8-deep (MLP=8).
        #pragma unroll 1
        for (int r0 = 0; r0 < WROWS; r0 += 8) {
            float2 v[8];
            #pragma unroll
            for (int j = 0; j < 8; j++) {
                const int r = r0 + j;
                const int mt = r >> 4, rr = (r >> 3) & 1, gg = r & 7;
                const int src_lane = 4 * gg + 2 * mt + rr;
                const int kk = __shfl_sync(0xFFFFFFFFu, kw, src_lane);
                v[j] = reinterpret_cast<const float2*>(cb + (size_t)kk * DQ)[lane];
            }
            #pragma unroll
            for (int j = 0; j < 8; j++)
                reinterpret_cast<float2*>(
                    out + (size_t)(row_base + r0 + j) * DQ)[lane] = v[j];
        }
    }
}

extern "C" void kernel_launch(void* const* d_in, const int* in_sizes, int n_in,
                              void* d_out, int out_size) {
    const float* ze = (const float*)d_in[0];
    const float* cb = (const float*)d_in[1];
    float* out = (float*)d_out;
    const int n_tokens = in_sizes[0] / DQ;
    const int n_wtiles = n_tokens / WROWS;   // 16384

    prep_kernel<<<1, KC>>>(cb);
    cudaFuncSetAttribute(vq_main,
                         cudaFuncAttributeMaxDynamicSharedMemorySize, SMEM_TOTAL);
    vq_main<<<CTAS, THREADS, SMEM_TOTAL>>>(ze, cb, out, n_wtiles);
}